// round 1
// baseline (speedup 1.0000x reference)
#include <cuda_runtime.h>
#include <math.h>

#define BATCH   2
#define SEQ     2048
#define DMODEL  1024
#define NHEADS  16
#define HDIM    64
#define MTOT    (BATCH*SEQ)   // 4096

// ---- scratch (no cudaMalloc allowed; __device__ globals are the sanctioned path) ----
__device__ float g_q[(size_t)BATCH*NHEADS*SEQ*HDIM];   // [B,H,S,64] 16MB
__device__ float g_k[(size_t)BATCH*NHEADS*SEQ*HDIM];
__device__ float g_v[(size_t)BATCH*NHEADS*SEQ*HDIM];
__device__ float g_attn[(size_t)MTOT*DMODEL];          // [B,S,D]    16MB

// ============================================================================
// GEMM: C[M,N] = A[M,K] @ W[K,N] + bias ; M=4096, N=K=1024
// 128x128 block tile, BK=8, 256 threads, 8x8 per-thread microtile.
// HEADSPLIT=true writes C in [B,H,S,64] layout (for Q/K/V).
// ============================================================================
#define GBM 128
#define GBN 128
#define GBK 8

template <bool HEADSPLIT>
__global__ void __launch_bounds__(256) gemm_kernel(
    const float* __restrict__ A, const float* __restrict__ W,
    const float* __restrict__ bias, float* __restrict__ C)
{
    __shared__ float As[GBK][GBM];   // transposed A tile
    __shared__ float Ws[GBK][GBN];

    const int K = DMODEL, N = DMODEL;
    const int tid  = threadIdx.x;
    const int tx   = tid & 15;
    const int ty   = tid >> 4;
    const int brow = blockIdx.y * GBM;
    const int bcol = blockIdx.x * GBN;

    const int arow = tid >> 1;           // 0..127
    const int aseg = (tid & 1) * 4;      // 0 or 4
    const int wrow = tid >> 5;           // 0..7
    const int wcol = (tid & 31) * 4;     // 0..124

    float acc[8][8];
    #pragma unroll
    for (int i = 0; i < 8; i++)
        #pragma unroll
        for (int j = 0; j < 8; j++) acc[i][j] = 0.f;

    for (int kt = 0; kt < K; kt += GBK) {
        float4 av = *(const float4*)(A + (size_t)(brow + arow) * K + kt + aseg);
        float4 wv = *(const float4*)(W + (size_t)(kt + wrow) * N + bcol + wcol);
        As[aseg + 0][arow] = av.x;
        As[aseg + 1][arow] = av.y;
        As[aseg + 2][arow] = av.z;
        As[aseg + 3][arow] = av.w;
        *(float4*)&Ws[wrow][wcol] = wv;
        __syncthreads();

        #pragma unroll
        for (int k = 0; k < GBK; k++) {
            float a[8], b[8];
            *(float4*)&a[0] = *(const float4*)&As[k][ty * 8];
            *(float4*)&a[4] = *(const float4*)&As[k][ty * 8 + 4];
            *(float4*)&b[0] = *(const float4*)&Ws[k][tx * 8];
            *(float4*)&b[4] = *(const float4*)&Ws[k][tx * 8 + 4];
            #pragma unroll
            for (int i = 0; i < 8; i++)
                #pragma unroll
                for (int j = 0; j < 8; j++)
                    acc[i][j] += a[i] * b[j];
        }
        __syncthreads();
    }

    #pragma unroll
    for (int i = 0; i < 8; i++) {
        const int r = brow + ty * 8 + i;
        #pragma unroll
        for (int jv = 0; jv < 8; jv += 4) {
            const int col = bcol + tx * 8 + jv;
            float4 bb = *(const float4*)&bias[col];
            float4 v  = make_float4(acc[i][jv + 0] + bb.x,
                                    acc[i][jv + 1] + bb.y,
                                    acc[i][jv + 2] + bb.z,
                                    acc[i][jv + 3] + bb.w);
            float* dst;
            if (HEADSPLIT) {
                const int bidx = r >> 11;           // / SEQ
                const int s    = r & (SEQ - 1);
                const int hh   = col >> 6;          // / HDIM
                const int d    = col & (HDIM - 1);
                dst = C + (((size_t)(bidx * NHEADS + hh) * SEQ + s) * HDIM + d);
            } else {
                dst = C + (size_t)r * DMODEL + col;
            }
            *(float4*)dst = v;
        }
    }
}

// ============================================================================
// Flash attention: per (b,h) block handles 64 queries, streams 64-wide KV
// tiles. 256 threads, 4x4 per-thread microtiles for both S=QK^T and O=PV.
// Smem: Qt/Kt transposed [d][row] for conflict-free compute loads; Vs, Ps
// natural. Online softmax with 16-lane shuffle reductions.
// ============================================================================
#define APAD 68   // row stride (floats); 68*4B = 272B keeps float4 alignment

__global__ void __launch_bounds__(256) attn_kernel(
    const float* __restrict__ Q, const float* __restrict__ K,
    const float* __restrict__ V, float* __restrict__ O)
{
    extern __shared__ float smem[];
    float (*Qt)[APAD] = (float(*)[APAD])(smem);
    float (*Kt)[APAD] = (float(*)[APAD])(smem + 64 * APAD);
    float (*Vs)[APAD] = (float(*)[APAD])(smem + 2 * 64 * APAD);
    float (*Ps)[APAD] = (float(*)[APAD])(smem + 3 * 64 * APAD);

    const int tid = threadIdx.x;
    const int tx  = tid & 15;
    const int ty  = tid >> 4;
    const int q0  = blockIdx.x * 64;
    const int h   = blockIdx.y;
    const int b   = blockIdx.z;

    const size_t head_off = (size_t)(b * NHEADS + h) * SEQ * HDIM;
    const float* qp = Q + head_off;
    const float* kp = K + head_off;
    const float* vp = V + head_off;

    // Q load: transposed mapping (lane-rows distinct -> conflict-free STS)
    {
        const int row  = tid & 63;
        const int quad = tid >> 6;           // 0..3, owns d = quad*16 .. +15
        #pragma unroll
        for (int i = 0; i < 4; i++) {
            const int d0 = quad * 16 + i * 4;
            float4 t = *(const float4*)(qp + (size_t)(q0 + row) * HDIM + d0);
            Qt[d0 + 0][row] = t.x * 0.125f;   // pre-scale by 1/sqrt(64)
            Qt[d0 + 1][row] = t.y * 0.125f;
            Qt[d0 + 2][row] = t.z * 0.125f;
            Qt[d0 + 3][row] = t.w * 0.125f;
        }
    }

    float m_i[4], l_i[4], o[4][4];
    #pragma unroll
    for (int i = 0; i < 4; i++) {
        m_i[i] = -INFINITY; l_i[i] = 0.f;
        #pragma unroll
        for (int j = 0; j < 4; j++) o[i][j] = 0.f;
    }

    for (int kv0 = 0; kv0 < SEQ; kv0 += 64) {
        // K: transposed mapping
        {
            const int row  = tid & 63;
            const int quad = tid >> 6;
            #pragma unroll
            for (int i = 0; i < 4; i++) {
                const int d0 = quad * 16 + i * 4;
                float4 t = *(const float4*)(kp + (size_t)(kv0 + row) * HDIM + d0);
                Kt[d0 + 0][row] = t.x;
                Kt[d0 + 1][row] = t.y;
                Kt[d0 + 2][row] = t.z;
                Kt[d0 + 3][row] = t.w;
            }
        }
        // V: natural layout, coalesced float4
        #pragma unroll
        for (int i = 0; i < 4; i++) {
            const int vdx = tid + i * 256;
            const int row = vdx >> 4;
            const int d0  = (vdx & 15) * 4;
            float4 u = *(const float4*)(vp + (size_t)(kv0 + row) * HDIM + d0);
            *(float4*)&Vs[row][d0] = u;
        }
        __syncthreads();

        // S = Q K^T  (4x4 per thread)
        float s[4][4];
        #pragma unroll
        for (int i = 0; i < 4; i++)
            #pragma unroll
            for (int j = 0; j < 4; j++) s[i][j] = 0.f;
        #pragma unroll 8
        for (int d = 0; d < 64; d++) {
            float qv[4], kvv[4];
            *(float4*)qv  = *(const float4*)&Qt[d][ty * 4];
            *(float4*)kvv = *(const float4*)&Kt[d][tx * 4];
            #pragma unroll
            for (int i = 0; i < 4; i++)
                #pragma unroll
                for (int j = 0; j < 4; j++)
                    s[i][j] += qv[i] * kvv[j];
        }

        // online softmax per row (rows owned by 16-lane groups of same ty)
        #pragma unroll
        for (int i = 0; i < 4; i++) {
            float mx = fmaxf(fmaxf(s[i][0], s[i][1]), fmaxf(s[i][2], s[i][3]));
            #pragma unroll
            for (int off = 8; off >= 1; off >>= 1)
                mx = fmaxf(mx, __shfl_xor_sync(0xffffffffu, mx, off));
            const float mnew = fmaxf(m_i[i], mx);
            const float corr = __expf(m_i[i] - mnew);
            m_i[i] = mnew;
            float rs = 0.f;
            #pragma unroll
            for (int j = 0; j < 4; j++) {
                const float p = __expf(s[i][j] - mnew);
                s[i][j] = p;
                rs += p;
            }
            #pragma unroll
            for (int off = 8; off >= 1; off >>= 1)
                rs += __shfl_xor_sync(0xffffffffu, rs, off);
            l_i[i] = l_i[i] * corr + rs;
            #pragma unroll
            for (int j = 0; j < 4; j++) o[i][j] *= corr;
        }

        // publish P transposed: Ps[j][i]
        #pragma unroll
        for (int j = 0; j < 4; j++)
            *(float4*)&Ps[tx * 4 + j][ty * 4] =
                make_float4(s[0][j], s[1][j], s[2][j], s[3][j]);
        __syncthreads();

        // O += P V
        #pragma unroll 8
        for (int j = 0; j < 64; j++) {
            float pv[4], vv[4];
            *(float4*)pv = *(const float4*)&Ps[j][ty * 4];
            *(float4*)vv = *(const float4*)&Vs[j][tx * 4];
            #pragma unroll
            for (int i = 0; i < 4; i++)
                #pragma unroll
                for (int k2 = 0; k2 < 4; k2++)
                    o[i][k2] += pv[i] * vv[k2];
        }
        __syncthreads();   // protect Kt/Vs/Ps before next tile overwrites
    }

    // finalize + write [B,S,D]
    #pragma unroll
    for (int i = 0; i < 4; i++) {
        const float inv = 1.f / l_i[i];
        const int row = q0 + ty * 4 + i;
        float4 v = make_float4(o[i][0] * inv, o[i][1] * inv,
                               o[i][2] * inv, o[i][3] * inv);
        *(float4*)(O + (size_t)(b * SEQ + row) * DMODEL + h * HDIM + tx * 4) = v;
    }
}

// ============================================================================
// launch
// ============================================================================
extern "C" void kernel_launch(void* const* d_in, const int* in_sizes, int n_in,
                              void* d_out, int out_size)
{
    const float* x  = (const float*)d_in[0];
    const float* Wq = (const float*)d_in[1];
    const float* bq = (const float*)d_in[2];
    const float* Wk = (const float*)d_in[3];
    const float* bk = (const float*)d_in[4];
    const float* Wv = (const float*)d_in[5];
    const float* bv = (const float*)d_in[6];
    const float* Wo = (const float*)d_in[7];
    const float* bo = (const float*)d_in[8];
    float* out = (float*)d_out;

    void *pq, *pk, *pv, *pa;
    cudaGetSymbolAddress(&pq, g_q);
    cudaGetSymbolAddress(&pk, g_k);
    cudaGetSymbolAddress(&pv, g_v);
    cudaGetSymbolAddress(&pa, g_attn);

    dim3 ggrid(DMODEL / GBN, MTOT / GBM);   // 8 x 32
    gemm_kernel<true><<<ggrid, 256>>>(x, Wq, bq, (float*)pq);
    gemm_kernel<true><<<ggrid, 256>>>(x, Wk, bk, (float*)pk);
    gemm_kernel<true><<<ggrid, 256>>>(x, Wv, bv, (float*)pv);

    const size_t attn_smem = 4 * 64 * APAD * sizeof(float);  // ~68 KB
    cudaFuncSetAttribute(attn_kernel,
                         cudaFuncAttributeMaxDynamicSharedMemorySize,
                         (int)attn_smem);
    attn_kernel<<<dim3(SEQ / 64, NHEADS, BATCH), 256, attn_smem>>>(
        (const float*)pq, (const float*)pk, (const float*)pv, (float*)pa);

    gemm_kernel<false><<<ggrid, 256>>>((const float*)pa, Wo, bo, out);
}

// round 3
// speedup vs baseline: 2.2165x; 2.2165x over previous
#include <cuda_runtime.h>
#include <cuda_bf16.h>
#include <math.h>
#include <stdint.h>

#define BATCH 2
#define SEQ   2048
#define DM    1024
#define NH    16
#define HD    64
#define MTOT  (BATCH*SEQ)   // 4096

// ---------------- scratch (__device__ globals; no cudaMalloc allowed) -------
__device__ __nv_bfloat16 g_qh[(size_t)MTOT*DM];   // [B,H,S,64] hi
__device__ __nv_bfloat16 g_ql[(size_t)MTOT*DM];   // lo
__device__ __nv_bfloat16 g_kh[(size_t)MTOT*DM];
__device__ __nv_bfloat16 g_kl[(size_t)MTOT*DM];
__device__ __nv_bfloat16 g_vh[(size_t)MTOT*DM];
__device__ __nv_bfloat16 g_vl[(size_t)MTOT*DM];
__device__ float         g_attn[(size_t)MTOT*DM]; // [B,S,D] fp32

// ---------------- helpers ---------------------------------------------------
__device__ __forceinline__ void splitpack(float x, float y,
                                          unsigned &hi, unsigned &lo) {
    __nv_bfloat16 hx = __float2bfloat16(x);
    __nv_bfloat16 hy = __float2bfloat16(y);
    float lx = x - __bfloat162float(hx);
    float ly = y - __bfloat162float(hy);
    hi = ((unsigned)__bfloat16_as_ushort(hy) << 16) |
          (unsigned)__bfloat16_as_ushort(hx);
    lo = ((unsigned)__bfloat16_as_ushort(__float2bfloat16(ly)) << 16) |
          (unsigned)__bfloat16_as_ushort(__float2bfloat16(lx));
}

__device__ __forceinline__ void ldsm4(unsigned* r, const void* p) {
    unsigned a = (unsigned)__cvta_generic_to_shared(p);
    asm volatile("ldmatrix.sync.aligned.m8n8.x4.shared.b16 {%0,%1,%2,%3}, [%4];"
                 : "=r"(r[0]), "=r"(r[1]), "=r"(r[2]), "=r"(r[3]) : "r"(a));
}
__device__ __forceinline__ void ldsm4t(unsigned* r, const void* p) {
    unsigned a = (unsigned)__cvta_generic_to_shared(p);
    asm volatile("ldmatrix.sync.aligned.m8n8.x4.trans.shared.b16 {%0,%1,%2,%3}, [%4];"
                 : "=r"(r[0]), "=r"(r[1]), "=r"(r[2]), "=r"(r[3]) : "r"(a));
}
__device__ __forceinline__ void mma16816(float* c, const unsigned* a,
                                         const unsigned* b) {
    asm volatile(
        "mma.sync.aligned.m16n8k16.row.col.f32.bf16.bf16.f32 "
        "{%0,%1,%2,%3},{%4,%5,%6,%7},{%8,%9},{%0,%1,%2,%3};"
        : "+f"(c[0]), "+f"(c[1]), "+f"(c[2]), "+f"(c[3])
        : "r"(a[0]), "r"(a[1]), "r"(a[2]), "r"(a[3]), "r"(b[0]), "r"(b[1]));
}

// ============================================================================
// Split-bf16 GEMM: C[M,N] = A[M,K] @ W[K,N] + bias  (3-MMA hi/lo split)
// 128x128x32 tile, 256 thr, 8 warps (4m x 2n), warp 32x64.
// MODE 0: fp32 row-major out (final projection).
// MODE 1: bf16 hi/lo split out in [B,H,S,64] layout, scaled (QKV).
// ============================================================================
#define GBM 128
#define GBN 128
#define GBK 32
#define AST 40    // halves: 32 data + 8 pad
#define BST 136   // halves: 128 data + 8 pad

template <int MODE>
__global__ void __launch_bounds__(256, 2) mma_gemm(
    const float* __restrict__ A, const float* __restrict__ W,
    const float* __restrict__ bias, float scale,
    float* __restrict__ Cf,
    __nv_bfloat16* __restrict__ Chi, __nv_bfloat16* __restrict__ Clo)
{
    __shared__ unsigned short As[2][GBM][AST];  // [hi/lo][m][k]
    __shared__ unsigned short Bs[2][GBK][BST];  // [hi/lo][k][n]

    const int tid  = threadIdx.x;
    const int lane = tid & 31, warp = tid >> 5;
    const int wm = (warp >> 1) * 32, wn = (warp & 1) * 64;
    const int brow = blockIdx.y * GBM, bcol = blockIdx.x * GBN;

    const int a_row = tid >> 1, a_k = (tid & 1) * 16;
    const int b_k   = tid >> 3, b_n = (tid & 7) * 16;

    float acc[2][8][4];
    #pragma unroll
    for (int i = 0; i < 2; i++)
        #pragma unroll
        for (int j = 0; j < 8; j++)
            #pragma unroll
            for (int c = 0; c < 4; c++) acc[i][j][c] = 0.f;

    for (int kt = 0; kt < DM; kt += GBK) {
        #pragma unroll
        for (int v = 0; v < 4; v++) {
            float4 t = *(const float4*)(A + (size_t)(brow + a_row) * DM + kt + a_k + v * 4);
            unsigned h0, l0, h1, l1;
            splitpack(t.x, t.y, h0, l0);
            splitpack(t.z, t.w, h1, l1);
            *(unsigned*)&As[0][a_row][a_k + v * 4]     = h0;
            *(unsigned*)&As[0][a_row][a_k + v * 4 + 2] = h1;
            *(unsigned*)&As[1][a_row][a_k + v * 4]     = l0;
            *(unsigned*)&As[1][a_row][a_k + v * 4 + 2] = l1;
        }
        #pragma unroll
        for (int v = 0; v < 4; v++) {
            float4 t = *(const float4*)(W + (size_t)(kt + b_k) * DM + bcol + b_n + v * 4);
            unsigned h0, l0, h1, l1;
            splitpack(t.x, t.y, h0, l0);
            splitpack(t.z, t.w, h1, l1);
            *(unsigned*)&Bs[0][b_k][b_n + v * 4]     = h0;
            *(unsigned*)&Bs[0][b_k][b_n + v * 4 + 2] = h1;
            *(unsigned*)&Bs[1][b_k][b_n + v * 4]     = l0;
            *(unsigned*)&Bs[1][b_k][b_n + v * 4 + 2] = l1;
        }
        __syncthreads();

        #pragma unroll
        for (int ks = 0; ks < 2; ks++) {
            unsigned ah[2][4], al[2][4];
            #pragma unroll
            for (int mi = 0; mi < 2; mi++) {
                const int ar = wm + 16 * mi + (lane & 15);
                const int ac = ks * 16 + ((lane & 16) ? 8 : 0);
                ldsm4(ah[mi], &As[0][ar][ac]);
                ldsm4(al[mi], &As[1][ar][ac]);
            }
            #pragma unroll
            for (int nq = 0; nq < 4; nq++) {
                const int kr = ks * 16 + (lane & 7) + ((lane & 8) ? 8 : 0);
                const int nc = wn + nq * 16 + ((lane & 16) ? 8 : 0);
                unsigned bh[4], bl[4];
                ldsm4t(bh, &Bs[0][kr][nc]);
                ldsm4t(bl, &Bs[1][kr][nc]);
                #pragma unroll
                for (int mi = 0; mi < 2; mi++) {
                    mma16816(acc[mi][2 * nq],     ah[mi], bh + 0);
                    mma16816(acc[mi][2 * nq + 1], ah[mi], bh + 2);
                    mma16816(acc[mi][2 * nq],     ah[mi], bl + 0);
                    mma16816(acc[mi][2 * nq + 1], ah[mi], bl + 2);
                    mma16816(acc[mi][2 * nq],     al[mi], bh + 0);
                    mma16816(acc[mi][2 * nq + 1], al[mi], bh + 2);
                }
            }
        }
        __syncthreads();
    }

    const int g = lane >> 2, tg = lane & 3;
    #pragma unroll
    for (int mi = 0; mi < 2; mi++) {
        #pragma unroll
        for (int nf = 0; nf < 8; nf++) {
            const int col = bcol + wn + nf * 8 + 2 * tg;
            const float b0 = bias[col], b1 = bias[col + 1];
            #pragma unroll
            for (int half = 0; half < 2; half++) {
                const int row = brow + wm + 16 * mi + g + 8 * half;
                const float v0 = (acc[mi][nf][2 * half + 0] + b0) * scale;
                const float v1 = (acc[mi][nf][2 * half + 1] + b1) * scale;
                if (MODE == 0) {
                    *(float2*)(Cf + (size_t)row * DM + col) = make_float2(v0, v1);
                } else {
                    const int bb = row >> 11, s = row & (SEQ - 1);
                    const int hh = col >> 6,  d = col & (HD - 1);
                    const size_t idx = (((size_t)(bb * NH + hh) * SEQ + s) * HD + d);
                    unsigned hi, lo;
                    splitpack(v0, v1, hi, lo);
                    *(unsigned*)(Chi + idx) = hi;
                    *(unsigned*)(Clo + idx) = lo;
                }
            }
        }
    }
}

// ============================================================================
// Flash attention on tensor cores, bf16 hi/lo split operands.
// Block: 64 q-rows, 128 thr (4 warps, m16 each). KV tiles of 64.
// ============================================================================
#define QST 72   // halves: 64 data + 8 pad

__global__ void __launch_bounds__(128) mma_attn(
    const __nv_bfloat16* __restrict__ Qh, const __nv_bfloat16* __restrict__ Ql,
    const __nv_bfloat16* __restrict__ Kh, const __nv_bfloat16* __restrict__ Kl,
    const __nv_bfloat16* __restrict__ Vh, const __nv_bfloat16* __restrict__ Vl,
    float* __restrict__ O)
{
    extern __shared__ unsigned short sm[];
    unsigned short* Qsh = sm;
    unsigned short* Qsl = sm + 1 * 64 * QST;
    unsigned short* Ksh = sm + 2 * 64 * QST;
    unsigned short* Ksl = sm + 3 * 64 * QST;
    unsigned short* Vsh = sm + 4 * 64 * QST;
    unsigned short* Vsl = sm + 5 * 64 * QST;

    const int tid = threadIdx.x, lane = tid & 31, warp = tid >> 5;
    const int q0 = blockIdx.x * 64;
    const int h  = blockIdx.y,  b = blockIdx.z;
    const size_t hoff = (size_t)(b * NH + h) * SEQ * HD;

    const int lrow = tid >> 1, lseg = (tid & 1) * 32;   // halves

    #pragma unroll
    for (int v = 0; v < 4; v++) {
        const size_t go = hoff + (size_t)(q0 + lrow) * HD + lseg + v * 8;
        *(uint4*)&Qsh[lrow * QST + lseg + v * 8] = *(const uint4*)(Qh + go);
        *(uint4*)&Qsl[lrow * QST + lseg + v * 8] = *(const uint4*)(Ql + go);
    }
    __syncthreads();

    const int g = lane >> 2, tg = lane & 3;
    float m0 = -INFINITY, m1 = -INFINITY, l0 = 0.f, l1 = 0.f;
    float o[8][4];
    #pragma unroll
    for (int i = 0; i < 8; i++)
        #pragma unroll
        for (int c = 0; c < 4; c++) o[i][c] = 0.f;

    for (int kv0 = 0; kv0 < SEQ; kv0 += 64) {
        #pragma unroll
        for (int v = 0; v < 4; v++) {
            const size_t go = hoff + (size_t)(kv0 + lrow) * HD + lseg + v * 8;
            const int so = lrow * QST + lseg + v * 8;
            *(uint4*)&Ksh[so] = *(const uint4*)(Kh + go);
            *(uint4*)&Ksl[so] = *(const uint4*)(Kl + go);
            *(uint4*)&Vsh[so] = *(const uint4*)(Vh + go);
            *(uint4*)&Vsl[so] = *(const uint4*)(Vl + go);
        }
        __syncthreads();

        // ---- S = Q K^T (split) ----
        float s[8][4];
        #pragma unroll
        for (int i = 0; i < 8; i++)
            #pragma unroll
            for (int c = 0; c < 4; c++) s[i][c] = 0.f;

        #pragma unroll
        for (int ks = 0; ks < 4; ks++) {           // k = d
            unsigned ah[4], al[4];
            const int ar = warp * 16 + (lane & 15);
            const int ac = ks * 16 + ((lane & 16) ? 8 : 0);
            ldsm4(ah, &Qsh[ar * QST + ac]);
            ldsm4(al, &Qsl[ar * QST + ac]);
            #pragma unroll
            for (int nq = 0; nq < 4; nq++) {       // n = s (16 each)
                const int srow = nq * 16 + (lane & 7) + ((lane & 16) ? 8 : 0);
                const int dcol = ks * 16 + ((lane & 8) ? 8 : 0);
                unsigned bh[4], bl[4];
                ldsm4(bh, &Ksh[srow * QST + dcol]);
                ldsm4(bl, &Ksl[srow * QST + dcol]);
                mma16816(s[2 * nq],     ah, bh + 0);
                mma16816(s[2 * nq + 1], ah, bh + 2);
                mma16816(s[2 * nq],     ah, bl + 0);
                mma16816(s[2 * nq + 1], ah, bl + 2);
                mma16816(s[2 * nq],     al, bh + 0);
                mma16816(s[2 * nq + 1], al, bh + 2);
            }
        }

        // ---- online softmax (rows g and g+8, quad-owned) ----
        float mx0 = -INFINITY, mx1 = -INFINITY;
        #pragma unroll
        for (int i = 0; i < 8; i++) {
            mx0 = fmaxf(mx0, fmaxf(s[i][0], s[i][1]));
            mx1 = fmaxf(mx1, fmaxf(s[i][2], s[i][3]));
        }
        mx0 = fmaxf(mx0, __shfl_xor_sync(0xffffffffu, mx0, 1));
        mx0 = fmaxf(mx0, __shfl_xor_sync(0xffffffffu, mx0, 2));
        mx1 = fmaxf(mx1, __shfl_xor_sync(0xffffffffu, mx1, 1));
        mx1 = fmaxf(mx1, __shfl_xor_sync(0xffffffffu, mx1, 2));
        const float mn0 = fmaxf(m0, mx0), mn1 = fmaxf(m1, mx1);
        const float c0 = __expf(m0 - mn0), c1 = __expf(m1 - mn1);
        m0 = mn0; m1 = mn1;
        float rs0 = 0.f, rs1 = 0.f;
        #pragma unroll
        for (int i = 0; i < 8; i++) {
            s[i][0] = __expf(s[i][0] - mn0);
            s[i][1] = __expf(s[i][1] - mn0);
            s[i][2] = __expf(s[i][2] - mn1);
            s[i][3] = __expf(s[i][3] - mn1);
            rs0 += s[i][0] + s[i][1];
            rs1 += s[i][2] + s[i][3];
        }
        rs0 += __shfl_xor_sync(0xffffffffu, rs0, 1);
        rs0 += __shfl_xor_sync(0xffffffffu, rs0, 2);
        rs1 += __shfl_xor_sync(0xffffffffu, rs1, 1);
        rs1 += __shfl_xor_sync(0xffffffffu, rs1, 2);
        l0 = l0 * c0 + rs0;
        l1 = l1 * c1 + rs1;
        #pragma unroll
        for (int i = 0; i < 8; i++) {
            o[i][0] *= c0; o[i][1] *= c0;
            o[i][2] *= c1; o[i][3] *= c1;
        }

        // ---- split P into bf16 hi/lo a-fragments (register-only) ----
        unsigned ph[8][2], pl[8][2];
        #pragma unroll
        for (int i = 0; i < 8; i++) {
            splitpack(s[i][0], s[i][1], ph[i][0], pl[i][0]);
            splitpack(s[i][2], s[i][3], ph[i][1], pl[i][1]);
        }

        // ---- O += P V (split) ----
        #pragma unroll
        for (int kss = 0; kss < 4; kss++) {        // k = s
            unsigned ah2[4] = { ph[2 * kss][0], ph[2 * kss][1],
                                ph[2 * kss + 1][0], ph[2 * kss + 1][1] };
            unsigned al2[4] = { pl[2 * kss][0], pl[2 * kss][1],
                                pl[2 * kss + 1][0], pl[2 * kss + 1][1] };
            #pragma unroll
            for (int nq = 0; nq < 4; nq++) {       // n = d
                const int srow = kss * 16 + (lane & 7) + ((lane & 8) ? 8 : 0);
                const int dcol = nq * 16 + ((lane & 16) ? 8 : 0);
                unsigned bh[4], bl[4];
                ldsm4t(bh, &Vsh[srow * QST + dcol]);
                ldsm4t(bl, &Vsl[srow * QST + dcol]);
                mma16816(o[2 * nq],     ah2, bh + 0);
                mma16816(o[2 * nq + 1], ah2, bh + 2);
                mma16816(o[2 * nq],     ah2, bl + 0);
                mma16816(o[2 * nq + 1], ah2, bl + 2);
                mma16816(o[2 * nq],     al2, bh + 0);
                mma16816(o[2 * nq + 1], al2, bh + 2);
            }
        }
        __syncthreads();
    }

    // ---- finalize + write [B,S,D] ----
    const float i0 = 1.f / l0, i1 = 1.f / l1;
    #pragma unroll
    for (int nf = 0; nf < 8; nf++) {
        const int d  = h * HD + nf * 8 + 2 * tg;
        const int r0 = q0 + warp * 16 + g;
        *(float2*)(O + (size_t)(b * SEQ + r0) * DM + d) =
            make_float2(o[nf][0] * i0, o[nf][1] * i0);
        *(float2*)(O + (size_t)(b * SEQ + r0 + 8) * DM + d) =
            make_float2(o[nf][2] * i1, o[nf][3] * i1);
    }
}

// ============================================================================
// launch
// ============================================================================
extern "C" void kernel_launch(void* const* d_in, const int* in_sizes, int n_in,
                              void* d_out, int out_size)
{
    const float* x  = (const float*)d_in[0];
    const float* Wq = (const float*)d_in[1];
    const float* bq = (const float*)d_in[2];
    const float* Wk = (const float*)d_in[3];
    const float* bk = (const float*)d_in[4];
    const float* Wv = (const float*)d_in[5];
    const float* bv = (const float*)d_in[6];
    const float* Wo = (const float*)d_in[7];
    const float* bo = (const float*)d_in[8];
    float* out = (float*)d_out;

    void *qh, *ql, *kh, *kl, *vh, *vl, *pa;
    cudaGetSymbolAddress(&qh, g_qh);
    cudaGetSymbolAddress(&ql, g_ql);
    cudaGetSymbolAddress(&kh, g_kh);
    cudaGetSymbolAddress(&kl, g_kl);
    cudaGetSymbolAddress(&vh, g_vh);
    cudaGetSymbolAddress(&vl, g_vl);
    cudaGetSymbolAddress(&pa, g_attn);

    dim3 gg(DM / GBN, MTOT / GBM);   // (8, 32)
    mma_gemm<1><<<gg, 256>>>(x, Wq, bq, 0.125f, nullptr,
                             (__nv_bfloat16*)qh, (__nv_bfloat16*)ql);
    mma_gemm<1><<<gg, 256>>>(x, Wk, bk, 1.f, nullptr,
                             (__nv_bfloat16*)kh, (__nv_bfloat16*)kl);
    mma_gemm<1><<<gg, 256>>>(x, Wv, bv, 1.f, nullptr,
                             (__nv_bfloat16*)vh, (__nv_bfloat16*)vl);

    const int attn_smem = 6 * 64 * QST * sizeof(unsigned short);  // 55296
    cudaFuncSetAttribute(mma_attn,
                         cudaFuncAttributeMaxDynamicSharedMemorySize, attn_smem);
    mma_attn<<<dim3(SEQ / 64, NH, BATCH), 128, attn_smem>>>(
        (const __nv_bfloat16*)qh, (const __nv_bfloat16*)ql,
        (const __nv_bfloat16*)kh, (const __nv_bfloat16*)kl,
        (const __nv_bfloat16*)vh, (const __nv_bfloat16*)vl, (float*)pa);

    mma_gemm<0><<<gg, 256>>>((const float*)pa, Wo, bo, 1.f, out, nullptr, nullptr);
}

// round 5
// speedup vs baseline: 2.9950x; 1.3513x over previous
#include <cuda_runtime.h>
#include <cuda_bf16.h>
#include <math.h>
#include <stdint.h>

#define BATCH 2
#define SEQ   2048
#define DM    1024
#define NH    16
#define HD    64
#define MTOT  (BATCH*SEQ)   // 4096

typedef unsigned short ushort_t;

// ---------------- scratch (__device__ globals; no cudaMalloc allowed) -------
__device__ __nv_bfloat16 g_xh[(size_t)MTOT*DM];
__device__ __nv_bfloat16 g_xl[(size_t)MTOT*DM];
__device__ __nv_bfloat16 g_wqh[(size_t)DM*DM];
__device__ __nv_bfloat16 g_wql[(size_t)DM*DM];
__device__ __nv_bfloat16 g_wkh[(size_t)DM*DM];
__device__ __nv_bfloat16 g_wkl[(size_t)DM*DM];
__device__ __nv_bfloat16 g_wvh[(size_t)DM*DM];
__device__ __nv_bfloat16 g_wvl[(size_t)DM*DM];
__device__ __nv_bfloat16 g_woh[(size_t)DM*DM];
__device__ __nv_bfloat16 g_wol[(size_t)DM*DM];
__device__ __nv_bfloat16 g_qh[(size_t)MTOT*DM];   // [B,H,S,64]
__device__ __nv_bfloat16 g_ql[(size_t)MTOT*DM];
__device__ __nv_bfloat16 g_kh[(size_t)MTOT*DM];
__device__ __nv_bfloat16 g_kl[(size_t)MTOT*DM];
__device__ __nv_bfloat16 g_vh[(size_t)MTOT*DM];
__device__ __nv_bfloat16 g_vl[(size_t)MTOT*DM];
__device__ __nv_bfloat16 g_oh[(size_t)MTOT*DM];   // [B,S,D]
__device__ __nv_bfloat16 g_ol[(size_t)MTOT*DM];

// ---------------- helpers ---------------------------------------------------
__device__ __forceinline__ void splitpack(float x, float y,
                                          unsigned &hi, unsigned &lo) {
    __nv_bfloat16 hx = __float2bfloat16(x);
    __nv_bfloat16 hy = __float2bfloat16(y);
    float lx = x - __bfloat162float(hx);
    float ly = y - __bfloat162float(hy);
    hi = ((unsigned)__bfloat16_as_ushort(hy) << 16) |
          (unsigned)__bfloat16_as_ushort(hx);
    lo = ((unsigned)__bfloat16_as_ushort(__float2bfloat16(ly)) << 16) |
          (unsigned)__bfloat16_as_ushort(__float2bfloat16(lx));
}

__device__ __forceinline__ void ldsm4(unsigned* r, const void* p) {
    unsigned a = (unsigned)__cvta_generic_to_shared(p);
    asm volatile("ldmatrix.sync.aligned.m8n8.x4.shared.b16 {%0,%1,%2,%3}, [%4];"
                 : "=r"(r[0]), "=r"(r[1]), "=r"(r[2]), "=r"(r[3]) : "r"(a));
}
__device__ __forceinline__ void ldsm4t(unsigned* r, const void* p) {
    unsigned a = (unsigned)__cvta_generic_to_shared(p);
    asm volatile("ldmatrix.sync.aligned.m8n8.x4.trans.shared.b16 {%0,%1,%2,%3}, [%4];"
                 : "=r"(r[0]), "=r"(r[1]), "=r"(r[2]), "=r"(r[3]) : "r"(a));
}
__device__ __forceinline__ void mma16816(float* c, const unsigned* a,
                                         const unsigned* b) {
    asm volatile(
        "mma.sync.aligned.m16n8k16.row.col.f32.bf16.bf16.f32 "
        "{%0,%1,%2,%3},{%4,%5,%6,%7},{%8,%9},{%0,%1,%2,%3};"
        : "+f"(c[0]), "+f"(c[1]), "+f"(c[2]), "+f"(c[3])
        : "r"(a[0]), "r"(a[1]), "r"(a[2]), "r"(a[3]), "r"(b[0]), "r"(b[1]));
}
__device__ __forceinline__ void cpa16(void* dst, const void* src) {
    unsigned d = (unsigned)__cvta_generic_to_shared(dst);
    asm volatile("cp.async.cg.shared.global [%0], [%1], 16;" :: "r"(d), "l"(src));
}
__device__ __forceinline__ void cpa_commit() {
    asm volatile("cp.async.commit_group;");
}
template <int N> __device__ __forceinline__ void cpa_wait() {
    asm volatile("cp.async.wait_group %0;" :: "n"(N));
}

// ============================================================================
// prep: fp32 -> bf16 hi/lo planes
// ============================================================================
__global__ void split_kernel(const float2* __restrict__ src,
                             unsigned* __restrict__ hi,
                             unsigned* __restrict__ lo, int n2)
{
    for (int i = blockIdx.x * blockDim.x + threadIdx.x; i < n2;
         i += gridDim.x * blockDim.x) {
        float2 v = src[i];
        unsigned h, l;
        splitpack(v.x, v.y, h, l);
        hi[i] = h;
        lo[i] = l;
    }
}

// ============================================================================
// Split-bf16 GEMM, cp.async double-buffered. C = A@W + bias (3-term split).
// 128x128x32, 256 thr, 8 warps (4m x 2n), warp 32x64.
// MODE 0: fp32 row-major out. MODE 1: bf16 hi/lo [B,H,S,64] out, scaled.
// ============================================================================
#define GBK 32
#define AST 40    // halves; 80B stride
#define BST 136   // halves; 272B stride

#define A_PL  (128*AST)
#define A_STG (2*A_PL)
#define B_PL  (GBK*BST)
#define B_STG (2*B_PL)
#define GEMM_SMEM ((2*A_STG + 2*B_STG)*2)   // 75776 bytes

template <int MODE>
__global__ void __launch_bounds__(256, 2) mma_gemm(
    const __nv_bfloat16* __restrict__ Ah, const __nv_bfloat16* __restrict__ Al,
    const __nv_bfloat16* __restrict__ Wh, const __nv_bfloat16* __restrict__ Wl,
    const float* __restrict__ bias, float scale,
    float* __restrict__ Cf,
    __nv_bfloat16* __restrict__ Chi, __nv_bfloat16* __restrict__ Clo)
{
    extern __shared__ ushort_t gsm[];
    ushort_t* Asm = gsm;
    ushort_t* Bsm = gsm + 2 * A_STG;

    const int tid  = threadIdx.x;
    const int lane = tid & 31, warp = tid >> 5;
    const int wm = (warp >> 1) * 32, wn = (warp & 1) * 64;
    const int brow = blockIdx.y * 128, bcol = blockIdx.x * 128;

    const int a_row = tid >> 2, a_c = (tid & 3) * 8;
    const int b_row = tid >> 4, b_c = (tid & 15) * 8;

    auto load_tile = [&](int stage, int kt) {
        #pragma unroll
        for (int p = 0; p < 2; p++) {
            const __nv_bfloat16* Ap = p ? Al : Ah;
            #pragma unroll
            for (int r = 0; r < 2; r++) {
                const int row = a_row + r * 64;
                cpa16(&Asm[stage * A_STG + p * A_PL + row * AST + a_c],
                      Ap + (size_t)(brow + row) * DM + kt + a_c);
            }
        }
        #pragma unroll
        for (int p = 0; p < 2; p++) {
            const __nv_bfloat16* Wp = p ? Wl : Wh;
            #pragma unroll
            for (int r = 0; r < 2; r++) {
                const int row = b_row + r * 16;
                cpa16(&Bsm[stage * B_STG + p * B_PL + row * BST + b_c],
                      Wp + (size_t)(kt + row) * DM + bcol + b_c);
            }
        }
    };

    float acc[2][8][4];
    #pragma unroll
    for (int i = 0; i < 2; i++)
        #pragma unroll
        for (int j = 0; j < 8; j++)
            #pragma unroll
            for (int c = 0; c < 4; c++) acc[i][j][c] = 0.f;

    load_tile(0, 0);  cpa_commit();
    load_tile(1, GBK); cpa_commit();

    const int NIT = DM / GBK;   // 32
    for (int it = 0; it < NIT; it++) {
        if (it < NIT - 1) cpa_wait<1>(); else cpa_wait<0>();
        __syncthreads();

        const int stage = it & 1;
        ushort_t* A0 = Asm + stage * A_STG;
        ushort_t* A1 = A0 + A_PL;
        ushort_t* B0 = Bsm + stage * B_STG;
        ushort_t* B1 = B0 + B_PL;

        #pragma unroll
        for (int ks = 0; ks < 2; ks++) {
            unsigned ah[2][4], al[2][4];
            #pragma unroll
            for (int mi = 0; mi < 2; mi++) {
                const int ar = wm + 16 * mi + (lane & 15);
                const int ac = ks * 16 + ((lane & 16) ? 8 : 0);
                ldsm4(ah[mi], &A0[ar * AST + ac]);
                ldsm4(al[mi], &A1[ar * AST + ac]);
            }
            #pragma unroll
            for (int nq = 0; nq < 4; nq++) {
                const int kr = ks * 16 + (lane & 7) + ((lane & 8) ? 8 : 0);
                const int nc = wn + nq * 16 + ((lane & 16) ? 8 : 0);
                unsigned bh[4], bl[4];
                ldsm4t(bh, &B0[kr * BST + nc]);
                ldsm4t(bl, &B1[kr * BST + nc]);
                #pragma unroll
                for (int mi = 0; mi < 2; mi++) {
                    mma16816(acc[mi][2 * nq],     ah[mi], bh + 0);
                    mma16816(acc[mi][2 * nq + 1], ah[mi], bh + 2);
                    mma16816(acc[mi][2 * nq],     ah[mi], bl + 0);
                    mma16816(acc[mi][2 * nq + 1], ah[mi], bl + 2);
                    mma16816(acc[mi][2 * nq],     al[mi], bh + 0);
                    mma16816(acc[mi][2 * nq + 1], al[mi], bh + 2);
                }
            }
        }
        __syncthreads();
        if (it + 2 < NIT) { load_tile(stage, (it + 2) * GBK); cpa_commit(); }
    }

    const int g = lane >> 2, tg = lane & 3;
    #pragma unroll
    for (int mi = 0; mi < 2; mi++) {
        #pragma unroll
        for (int nf = 0; nf < 8; nf++) {
            const int col = bcol + wn + nf * 8 + 2 * tg;
            const float b0 = bias[col], b1 = bias[col + 1];
            #pragma unroll
            for (int half = 0; half < 2; half++) {
                const int row = brow + wm + 16 * mi + g + 8 * half;
                const float v0 = (acc[mi][nf][2 * half + 0] + b0) * scale;
                const float v1 = (acc[mi][nf][2 * half + 1] + b1) * scale;
                if (MODE == 0) {
                    *(float2*)(Cf + (size_t)row * DM + col) = make_float2(v0, v1);
                } else {
                    const int bb = row >> 11, s = row & (SEQ - 1);
                    const int hh = col >> 6,  d = col & (HD - 1);
                    const size_t idx = (((size_t)(bb * NH + hh) * SEQ + s) * HD + d);
                    unsigned hi, lo;
                    splitpack(v0, v1, hi, lo);
                    *(unsigned*)(Chi + idx) = hi;
                    *(unsigned*)(Clo + idx) = lo;
                }
            }
        }
    }
}

// ============================================================================
// Flash attention, split-bf16 MMA, cp.async double-buffered KV.
// CTA: 128 q-rows, 128 thr (4 warps, each 32 q x 64 kv, mi=2). KV tile 64.
// ============================================================================
#define QST 72
#define Q_PL   (128*QST)
#define KV_PL  (64*QST)
#define KV_STG (4*KV_PL)
#define KV_BASE (2*Q_PL)
#define ATTN_SMEM ((2*Q_PL + 2*KV_STG)*2)   // 110592 bytes

__global__ void __launch_bounds__(128, 2) mma_attn(
    const __nv_bfloat16* __restrict__ Qh, const __nv_bfloat16* __restrict__ Ql,
    const __nv_bfloat16* __restrict__ Kh, const __nv_bfloat16* __restrict__ Kl,
    const __nv_bfloat16* __restrict__ Vh, const __nv_bfloat16* __restrict__ Vl,
    __nv_bfloat16* __restrict__ Ohi, __nv_bfloat16* __restrict__ Olo)
{
    extern __shared__ ushort_t sm[];

    const int tid = threadIdx.x, lane = tid & 31, warp = tid >> 5;
    const int q0 = blockIdx.x * 128;
    const int h  = blockIdx.y,  b = blockIdx.z;
    const size_t hoff = (size_t)(b * NH + h) * SEQ * HD;

    const __nv_bfloat16* kvp[4] = { Kh + hoff, Kl + hoff, Vh + hoff, Vl + hoff };

    const int lr = tid >> 3, lc = (tid & 7) * 8;

    auto load_kv = [&](int stage, int kv0) {
        #pragma unroll
        for (int k = 0; k < 16; k++) {
            const int p   = k >> 2;
            const int row = lr + (k & 3) * 16;
            cpa16(&sm[KV_BASE + stage * KV_STG + p * KV_PL + row * QST + lc],
                  kvp[p] + (size_t)(kv0 + row) * HD + lc);
        }
    };

    {
        const __nv_bfloat16* qp[2] = { Qh + hoff, Ql + hoff };
        #pragma unroll
        for (int k = 0; k < 16; k++) {
            const int p   = k >> 3;
            const int row = lr + (k & 7) * 16;
            cpa16(&sm[p * Q_PL + row * QST + lc],
                  qp[p] + (size_t)(q0 + row) * HD + lc);
        }
    }
    load_kv(0, 0); cpa_commit();
    load_kv(1, 64); cpa_commit();

    const int g = lane >> 2, tg = lane & 3;
    float m[2][2], l[2][2], o[2][8][4];
    #pragma unroll
    for (int mi = 0; mi < 2; mi++) {
        m[mi][0] = -INFINITY; m[mi][1] = -INFINITY;
        l[mi][0] = 0.f;       l[mi][1] = 0.f;
        #pragma unroll
        for (int i = 0; i < 8; i++)
            #pragma unroll
            for (int c = 0; c < 4; c++) o[mi][i][c] = 0.f;
    }

    const int NIT = SEQ / 64;   // 32
    for (int it = 0; it < NIT; it++) {
        if (it < NIT - 1) cpa_wait<1>(); else cpa_wait<0>();
        __syncthreads();

        const int stage = it & 1;
        ushort_t* Ksh = sm + KV_BASE + stage * KV_STG;
        ushort_t* Ksl = Ksh + KV_PL;
        ushort_t* Vsh = Ksl + KV_PL;
        ushort_t* Vsl = Vsh + KV_PL;

        // ---- S = Q K^T ----
        float s[2][8][4];
        #pragma unroll
        for (int mi = 0; mi < 2; mi++)
            #pragma unroll
            for (int i = 0; i < 8; i++)
                #pragma unroll
                for (int c = 0; c < 4; c++) s[mi][i][c] = 0.f;

        #pragma unroll
        for (int ks = 0; ks < 4; ks++) {
            unsigned ah[2][4], al[2][4];
            #pragma unroll
            for (int mi = 0; mi < 2; mi++) {
                const int ar = warp * 32 + 16 * mi + (lane & 15);
                const int ac = ks * 16 + ((lane & 16) ? 8 : 0);
                ldsm4(ah[mi], &sm[0 * Q_PL + ar * QST + ac]);
                ldsm4(al[mi], &sm[1 * Q_PL + ar * QST + ac]);
            }
            #pragma unroll
            for (int nq = 0; nq < 4; nq++) {
                // FIXED (round-3 bug): n-split on lane&16, k-split on lane&8
                const int srow = nq * 16 + (lane & 7) + ((lane & 16) ? 8 : 0);
                const int dcol = ks * 16 + ((lane & 8) ? 8 : 0);
                unsigned bh[4], bl[4];
                ldsm4(bh, &Ksh[srow * QST + dcol]);
                ldsm4(bl, &Ksl[srow * QST + dcol]);
                #pragma unroll
                for (int mi = 0; mi < 2; mi++) {
                    mma16816(s[mi][2 * nq],     ah[mi], bh + 0);
                    mma16816(s[mi][2 * nq + 1], ah[mi], bh + 2);
                    mma16816(s[mi][2 * nq],     ah[mi], bl + 0);
                    mma16816(s[mi][2 * nq + 1], ah[mi], bl + 2);
                    mma16816(s[mi][2 * nq],     al[mi], bh + 0);
                    mma16816(s[mi][2 * nq + 1], al[mi], bh + 2);
                }
            }
        }

        // ---- online softmax + split P ----
        unsigned ph[2][8][2], pl[2][8][2];
        #pragma unroll
        for (int mi = 0; mi < 2; mi++) {
            float mx0 = -INFINITY, mx1 = -INFINITY;
            #pragma unroll
            for (int i = 0; i < 8; i++) {
                mx0 = fmaxf(mx0, fmaxf(s[mi][i][0], s[mi][i][1]));
                mx1 = fmaxf(mx1, fmaxf(s[mi][i][2], s[mi][i][3]));
            }
            mx0 = fmaxf(mx0, __shfl_xor_sync(0xffffffffu, mx0, 1));
            mx0 = fmaxf(mx0, __shfl_xor_sync(0xffffffffu, mx0, 2));
            mx1 = fmaxf(mx1, __shfl_xor_sync(0xffffffffu, mx1, 1));
            mx1 = fmaxf(mx1, __shfl_xor_sync(0xffffffffu, mx1, 2));
            const float mn0 = fmaxf(m[mi][0], mx0), mn1 = fmaxf(m[mi][1], mx1);
            const float c0 = __expf(m[mi][0] - mn0), c1 = __expf(m[mi][1] - mn1);
            m[mi][0] = mn0; m[mi][1] = mn1;
            float rs0 = 0.f, rs1 = 0.f;
            #pragma unroll
            for (int i = 0; i < 8; i++) {
                s[mi][i][0] = __expf(s[mi][i][0] - mn0);
                s[mi][i][1] = __expf(s[mi][i][1] - mn0);
                s[mi][i][2] = __expf(s[mi][i][2] - mn1);
                s[mi][i][3] = __expf(s[mi][i][3] - mn1);
                rs0 += s[mi][i][0] + s[mi][i][1];
                rs1 += s[mi][i][2] + s[mi][i][3];
            }
            rs0 += __shfl_xor_sync(0xffffffffu, rs0, 1);
            rs0 += __shfl_xor_sync(0xffffffffu, rs0, 2);
            rs1 += __shfl_xor_sync(0xffffffffu, rs1, 1);
            rs1 += __shfl_xor_sync(0xffffffffu, rs1, 2);
            l[mi][0] = l[mi][0] * c0 + rs0;
            l[mi][1] = l[mi][1] * c1 + rs1;
            #pragma unroll
            for (int i = 0; i < 8; i++) {
                o[mi][i][0] *= c0; o[mi][i][1] *= c0;
                o[mi][i][2] *= c1; o[mi][i][3] *= c1;
                splitpack(s[mi][i][0], s[mi][i][1], ph[mi][i][0], pl[mi][i][0]);
                splitpack(s[mi][i][2], s[mi][i][3], ph[mi][i][1], pl[mi][i][1]);
            }
        }

        // ---- O += P V ----
        #pragma unroll
        for (int kss = 0; kss < 4; kss++) {
            unsigned a2h[2][4], a2l[2][4];
            #pragma unroll
            for (int mi = 0; mi < 2; mi++) {
                a2h[mi][0] = ph[mi][2 * kss][0];     a2h[mi][1] = ph[mi][2 * kss][1];
                a2h[mi][2] = ph[mi][2 * kss + 1][0]; a2h[mi][3] = ph[mi][2 * kss + 1][1];
                a2l[mi][0] = pl[mi][2 * kss][0];     a2l[mi][1] = pl[mi][2 * kss][1];
                a2l[mi][2] = pl[mi][2 * kss + 1][0]; a2l[mi][3] = pl[mi][2 * kss + 1][1];
            }
            #pragma unroll
            for (int nq = 0; nq < 4; nq++) {
                const int srow = kss * 16 + (lane & 7) + ((lane & 8) ? 8 : 0);
                const int dcol = nq * 16 + ((lane & 16) ? 8 : 0);
                unsigned bh[4], bl[4];
                ldsm4t(bh, &Vsh[srow * QST + dcol]);
                ldsm4t(bl, &Vsl[srow * QST + dcol]);
                #pragma unroll
                for (int mi = 0; mi < 2; mi++) {
                    mma16816(o[mi][2 * nq],     a2h[mi], bh + 0);
                    mma16816(o[mi][2 * nq + 1], a2h[mi], bh + 2);
                    mma16816(o[mi][2 * nq],     a2h[mi], bl + 0);
                    mma16816(o[mi][2 * nq + 1], a2h[mi], bl + 2);
                    mma16816(o[mi][2 * nq],     a2l[mi], bh + 0);
                    mma16816(o[mi][2 * nq + 1], a2l[mi], bh + 2);
                }
            }
        }
        __syncthreads();
        if (it + 2 < NIT) { load_kv(stage, (it + 2) * 64); cpa_commit(); }
    }

    // ---- finalize: write O hi/lo planes [B,S,D] ----
    #pragma unroll
    for (int mi = 0; mi < 2; mi++) {
        const float i0 = 1.f / l[mi][0], i1 = 1.f / l[mi][1];
        #pragma unroll
        for (int nf = 0; nf < 8; nf++) {
            const int d  = h * HD + nf * 8 + 2 * tg;
            const int r0 = q0 + warp * 32 + 16 * mi + g;
            unsigned hi, lo;
            splitpack(o[mi][nf][0] * i0, o[mi][nf][1] * i0, hi, lo);
            *(unsigned*)(Ohi + (size_t)(b * SEQ + r0) * DM + d) = hi;
            *(unsigned*)(Olo + (size_t)(b * SEQ + r0) * DM + d) = lo;
            splitpack(o[mi][nf][2] * i1, o[mi][nf][3] * i1, hi, lo);
            *(unsigned*)(Ohi + (size_t)(b * SEQ + r0 + 8) * DM + d) = hi;
            *(unsigned*)(Olo + (size_t)(b * SEQ + r0 + 8) * DM + d) = lo;
        }
    }
}

// ============================================================================
// launch
// ============================================================================
extern "C" void kernel_launch(void* const* d_in, const int* in_sizes, int n_in,
                              void* d_out, int out_size)
{
    const float* x  = (const float*)d_in[0];
    const float* Wq = (const float*)d_in[1];
    const float* bq = (const float*)d_in[2];
    const float* Wk = (const float*)d_in[3];
    const float* bk = (const float*)d_in[4];
    const float* Wv = (const float*)d_in[5];
    const float* bv = (const float*)d_in[6];
    const float* Wo = (const float*)d_in[7];
    const float* bo = (const float*)d_in[8];
    float* out = (float*)d_out;

    void *xh, *xl, *wqh, *wql, *wkh, *wkl, *wvh, *wvl, *woh, *wol;
    void *qh, *ql, *kh, *kl, *vh, *vl, *oh, *ol;
    cudaGetSymbolAddress(&xh, g_xh);   cudaGetSymbolAddress(&xl, g_xl);
    cudaGetSymbolAddress(&wqh, g_wqh); cudaGetSymbolAddress(&wql, g_wql);
    cudaGetSymbolAddress(&wkh, g_wkh); cudaGetSymbolAddress(&wkl, g_wkl);
    cudaGetSymbolAddress(&wvh, g_wvh); cudaGetSymbolAddress(&wvl, g_wvl);
    cudaGetSymbolAddress(&woh, g_woh); cudaGetSymbolAddress(&wol, g_wol);
    cudaGetSymbolAddress(&qh, g_qh);   cudaGetSymbolAddress(&ql, g_ql);
    cudaGetSymbolAddress(&kh, g_kh);   cudaGetSymbolAddress(&kl, g_kl);
    cudaGetSymbolAddress(&vh, g_vh);   cudaGetSymbolAddress(&vl, g_vl);
    cudaGetSymbolAddress(&oh, g_oh);   cudaGetSymbolAddress(&ol, g_ol);

    // prep splits
    split_kernel<<<512, 256>>>((const float2*)x,  (unsigned*)xh,  (unsigned*)xl,  MTOT*DM/2);
    split_kernel<<<256, 256>>>((const float2*)Wq, (unsigned*)wqh, (unsigned*)wql, DM*DM/2);
    split_kernel<<<256, 256>>>((const float2*)Wk, (unsigned*)wkh, (unsigned*)wkl, DM*DM/2);
    split_kernel<<<256, 256>>>((const float2*)Wv, (unsigned*)wvh, (unsigned*)wvl, DM*DM/2);
    split_kernel<<<256, 256>>>((const float2*)Wo, (unsigned*)woh, (unsigned*)wol, DM*DM/2);

    cudaFuncSetAttribute(mma_gemm<0>, cudaFuncAttributeMaxDynamicSharedMemorySize, GEMM_SMEM);
    cudaFuncSetAttribute(mma_gemm<1>, cudaFuncAttributeMaxDynamicSharedMemorySize, GEMM_SMEM);
    cudaFuncSetAttribute(mma_attn, cudaFuncAttributeMaxDynamicSharedMemorySize, ATTN_SMEM);

    dim3 gg(DM / 128, MTOT / 128);   // (8, 32)
    mma_gemm<1><<<gg, 256, GEMM_SMEM>>>(
        (const __nv_bfloat16*)xh, (const __nv_bfloat16*)xl,
        (const __nv_bfloat16*)wqh, (const __nv_bfloat16*)wql,
        bq, 0.125f, nullptr, (__nv_bfloat16*)qh, (__nv_bfloat16*)ql);
    mma_gemm<1><<<gg, 256, GEMM_SMEM>>>(
        (const __nv_bfloat16*)xh, (const __nv_bfloat16*)xl,
        (const __nv_bfloat16*)wkh, (const __nv_bfloat16*)wkl,
        bk, 1.f, nullptr, (__nv_bfloat16*)kh, (__nv_bfloat16*)kl);
    mma_gemm<1><<<gg, 256, GEMM_SMEM>>>(
        (const __nv_bfloat16*)xh, (const __nv_bfloat16*)xl,
        (const __nv_bfloat16*)wvh, (const __nv_bfloat16*)wvl,
        bv, 1.f, nullptr, (__nv_bfloat16*)vh, (__nv_bfloat16*)vl);

    mma_attn<<<dim3(SEQ / 128, NH, BATCH), 128, ATTN_SMEM>>>(
        (const __nv_bfloat16*)qh, (const __nv_bfloat16*)ql,
        (const __nv_bfloat16*)kh, (const __nv_bfloat16*)kl,
        (const __nv_bfloat16*)vh, (const __nv_bfloat16*)vl,
        (__nv_bfloat16*)oh, (__nv_bfloat16*)ol);

    mma_gemm<0><<<gg, 256, GEMM_SMEM>>>(
        (const __nv_bfloat16*)oh, (const __nv_bfloat16*)ol,
        (const __nv_bfloat16*)woh, (const __nv_bfloat16*)wol,
        bo, 1.f, out, nullptr, nullptr);
}